// round 6
// baseline (speedup 1.0000x reference)
#include <cuda_runtime.h>
#include <math.h>

#define BB   512
#define IN_  256
#define HH   512
#define NS_  4
#define SS_  128
#define CS_  128
#define KH   1280           // IN + NS*CS + HH
#define NPA  576            // 512 push + 12 act + 52 pad
#define KSPL 4              // split-K factor

// ---------------------------------------------------------------------------
// Scratch
// ---------------------------------------------------------------------------
__device__ __align__(16) float g_Ph  [KSPL * BB * HH];    // gemm-h partials
__device__ __align__(16) float g_Ppa [KSPL * BB * NPA];   // gemm-pa partials
__device__ __align__(16) float g_push[BB * NS_ * CS_];
__device__ __align__(16) float g_logits[BB * 12];
__device__ __align__(16) float g_probs [BB * 12];

__device__ __forceinline__ float tanh_fast(float x) {
    float y;
    asm("tanh.approx.f32 %0, %1;" : "=f"(y) : "f"(x));
    return y;
}

// ---------------------------------------------------------------------------
// Virtual operand loaders (float4, k % 4 == 0; region bounds are multiples
// of 16 so a BK=16 tile never straddles regions for A/W of gemm-h)
// ---------------------------------------------------------------------------
__device__ __forceinline__ float4 ldX(const float* __restrict__ inputs,
                                      const float* __restrict__ stacks,
                                      const float* __restrict__ core,
                                      int m, int k) {
    if (k < IN_) {
        return *(const float4*)(inputs + m * IN_ + k);
    } else if (k < IN_ + NS_ * CS_) {
        int c = k - IN_;
        return *(const float4*)(stacks + ((size_t)(m * NS_ + (c >> 7))) * (SS_ * CS_) + (c & 127));
    } else {
        return *(const float4*)(core + m * HH + (k - IN_ - NS_ * CS_));
    }
}

__device__ __forceinline__ float4 ldWc(const float* __restrict__ W_ih,
                                       const float* __restrict__ W_hh,
                                       int n, int k) {
    if (k < IN_ + NS_ * CS_)
        return *(const float4*)(W_ih + (size_t)n * (IN_ + NS_ * CS_) + k);
    else
        return *(const float4*)(W_hh + (size_t)n * HH + (k - IN_ - NS_ * CS_));
}

__device__ __forceinline__ float4 ldWpa(const float* __restrict__ W_push,
                                        const float* __restrict__ W_act,
                                        int n, int k) {
    if (n < 512)       return *(const float4*)(W_push + (size_t)n * HH + k);
    else if (n < 524)  return *(const float4*)(W_act + (size_t)(n - 512) * HH + k);
    else               return make_float4(0.f, 0.f, 0.f, 0.f);
}

// ---------------------------------------------------------------------------
// GEMM (split-K partials): P[z, m, n] = sum_{k in split z} A[m,k] * W[n,k]
// BM=64, BN=64, BK=16, 128 threads, 8x4 per thread.
// MODE 0: gemm-h   (A = virtual X,   W = [W_ih|W_hh],   N=512, K=1280)
// MODE 1: gemm-pa  (A = h,           W = [W_push;W_act;0], N=576, K=512)
// ---------------------------------------------------------------------------
template <int MODE>
__global__ void __launch_bounds__(128)
gemm_split(const float* __restrict__ Ah,
           const float* __restrict__ inputs,
           const float* __restrict__ stacks,
           const float* __restrict__ core,
           const float* __restrict__ W_ih,
           const float* __restrict__ W_hh,
           const float* __restrict__ W_push,
           const float* __restrict__ W_act,
           float* __restrict__ P) {
    __shared__ __align__(16) float As[16][68];
    __shared__ __align__(16) float Bs[16][68];

    constexpr int N  = (MODE == 0) ? HH : NPA;
    constexpr int NT = (MODE == 0) ? (KH / KSPL / 16) : (HH / KSPL / 16); // 20 / 8

    const int tid = threadIdx.x;
    const int m0 = blockIdx.y * 64;
    const int n0 = blockIdx.x * 64;
    const int z  = blockIdx.z;
    const int k0 = z * NT * 16;

    const int lr = tid >> 2;            // 0..31
    const int lc = (tid & 3) << 2;      // 0,4,8,12
    const int tx = tid & 15;            // n (x4)
    const int ty = tid >> 4;            // m (x8)

    float acc[8][4] = {};

    // prefetch tile 0
    float4 a0, a1, b0, b1;
    {
        int k = k0 + lc;
        if (MODE == 0) {
            a0 = ldX(inputs, stacks, core, m0 + lr, k);
            a1 = ldX(inputs, stacks, core, m0 + lr + 32, k);
            b0 = ldWc(W_ih, W_hh, n0 + lr, k);
            b1 = ldWc(W_ih, W_hh, n0 + lr + 32, k);
        } else {
            a0 = *(const float4*)(Ah + (m0 + lr) * HH + k);
            a1 = *(const float4*)(Ah + (m0 + lr + 32) * HH + k);
            b0 = ldWpa(W_push, W_act, n0 + lr, k);
            b1 = ldWpa(W_push, W_act, n0 + lr + 32, k);
        }
    }

    for (int kt = 0; kt < NT; ++kt) {
        As[lc + 0][lr] = a0.x; As[lc + 1][lr] = a0.y;
        As[lc + 2][lr] = a0.z; As[lc + 3][lr] = a0.w;
        As[lc + 0][lr + 32] = a1.x; As[lc + 1][lr + 32] = a1.y;
        As[lc + 2][lr + 32] = a1.z; As[lc + 3][lr + 32] = a1.w;
        Bs[lc + 0][lr] = b0.x; Bs[lc + 1][lr] = b0.y;
        Bs[lc + 2][lr] = b0.z; Bs[lc + 3][lr] = b0.w;
        Bs[lc + 0][lr + 32] = b1.x; Bs[lc + 1][lr + 32] = b1.y;
        Bs[lc + 2][lr + 32] = b1.z; Bs[lc + 3][lr + 32] = b1.w;
        __syncthreads();

        if (kt + 1 < NT) {
            int k = k0 + (kt + 1) * 16 + lc;
            if (MODE == 0) {
                a0 = ldX(inputs, stacks, core, m0 + lr, k);
                a1 = ldX(inputs, stacks, core, m0 + lr + 32, k);
                b0 = ldWc(W_ih, W_hh, n0 + lr, k);
                b1 = ldWc(W_ih, W_hh, n0 + lr + 32, k);
            } else {
                a0 = *(const float4*)(Ah + (m0 + lr) * HH + k);
                a1 = *(const float4*)(Ah + (m0 + lr + 32) * HH + k);
                b0 = ldWpa(W_push, W_act, n0 + lr, k);
                b1 = ldWpa(W_push, W_act, n0 + lr + 32, k);
            }
        }

        #pragma unroll
        for (int kk = 0; kk < 16; ++kk) {
            float ar[8], br[4];
            *reinterpret_cast<float4*>(&ar[0]) = *(const float4*)&As[kk][ty * 8];
            *reinterpret_cast<float4*>(&ar[4]) = *(const float4*)&As[kk][ty * 8 + 4];
            *reinterpret_cast<float4*>(&br[0]) = *(const float4*)&Bs[kk][tx * 4];
            #pragma unroll
            for (int i = 0; i < 8; ++i)
                #pragma unroll
                for (int j = 0; j < 4; ++j)
                    acc[i][j] = fmaf(ar[i], br[j], acc[i][j]);
        }
        __syncthreads();
    }

    float* Pz = P + (size_t)z * BB * N;
    #pragma unroll
    for (int i = 0; i < 8; ++i) {
        float4 o = make_float4(acc[i][0], acc[i][1], acc[i][2], acc[i][3]);
        *(float4*)(Pz + (m0 + ty * 8 + i) * N + n0 + tx * 4) = o;
    }
}

// ---------------------------------------------------------------------------
// Epilogue h: h = tanh(sum_z P[z] + b_ih + b_hh)
// ---------------------------------------------------------------------------
__global__ void __launch_bounds__(256)
epi_h(const float* __restrict__ P,
      const float* __restrict__ b_ih, const float* __restrict__ b_hh,
      float* __restrict__ h) {
    int idx = blockIdx.x * 256 + threadIdx.x;   // float4 index, 65536 total
    int e = idx << 2;
    int n = e & (HH - 1);
    float4 s = *(const float4*)(P + e);
    float4 s1 = *(const float4*)(P + BB * HH + e);
    float4 s2 = *(const float4*)(P + 2 * BB * HH + e);
    float4 s3 = *(const float4*)(P + 3 * BB * HH + e);
    float4 bi = *(const float4*)(b_ih + n);
    float4 bh = *(const float4*)(b_hh + n);
    float4 o;
    o.x = tanh_fast(s.x + s1.x + s2.x + s3.x + bi.x + bh.x);
    o.y = tanh_fast(s.y + s1.y + s2.y + s3.y + bi.y + bh.y);
    o.z = tanh_fast(s.z + s1.z + s2.z + s3.z + bi.z + bh.z);
    o.w = tanh_fast(s.w + s1.w + s2.w + s3.w + bi.w + bh.w);
    *(float4*)(h + e) = o;
}

// ---------------------------------------------------------------------------
// Epilogue pa: push = sum_z Q[z] + b_push (n<512), logits = ... + b_act (512..523)
// ---------------------------------------------------------------------------
__global__ void __launch_bounds__(256)
epi_pa(const float* __restrict__ Q,
       const float* __restrict__ b_push, const float* __restrict__ b_act,
       float* __restrict__ push, float* __restrict__ logits) {
    int idx = blockIdx.x * 256 + threadIdx.x;   // float4 index over 512*576
    int e = idx << 2;
    int m = e / NPA;
    int n = e - m * NPA;
    if (n >= 524) return;
    float4 s = *(const float4*)(Q + e);
    float4 s1 = *(const float4*)(Q + BB * NPA + e);
    float4 s2 = *(const float4*)(Q + 2 * BB * NPA + e);
    float4 s3 = *(const float4*)(Q + 3 * BB * NPA + e);
    float4 o;
    o.x = s.x + s1.x + s2.x + s3.x;
    o.y = s.y + s1.y + s2.y + s3.y;
    o.z = s.z + s1.z + s2.z + s3.z;
    o.w = s.w + s1.w + s2.w + s3.w;
    if (n < 512) {
        float4 b = *(const float4*)(b_push + n);
        o.x += b.x; o.y += b.y; o.z += b.z; o.w += b.w;
        *(float4*)(push + m * 512 + n) = o;
    } else {
        float4 b = *(const float4*)(b_act + (n - 512));
        o.x += b.x; o.y += b.y; o.z += b.z; o.w += b.w;
        *(float4*)(logits + m * 12 + (n - 512)) = o;
    }
}

// ---------------------------------------------------------------------------
// probs: joint softmax over 12 logits per batch row (once, not per stack thread)
// ---------------------------------------------------------------------------
__global__ void __launch_bounds__(256)
probs_kernel(const float* __restrict__ logits, float* __restrict__ probs) {
    int b = blockIdx.x * 256 + threadIdx.x;
    if (b >= BB) return;
    float l[12];
    #pragma unroll
    for (int i = 0; i < 12; ++i) l[i] = logits[b * 12 + i];
    float mx = l[0];
    #pragma unroll
    for (int i = 1; i < 12; ++i) mx = fmaxf(mx, l[i]);
    float s = 0.f;
    #pragma unroll
    for (int i = 0; i < 12; ++i) { l[i] = expf(l[i] - mx); s += l[i]; }
    float inv = 1.f / s;
    #pragma unroll
    for (int i = 0; i < 12; ++i) probs[b * 12 + i] = l[i] * inv;
}

// ---------------------------------------------------------------------------
// Stack update v2: segment-batched. Thread = (g, col4, 8-row segment).
// grid 4096 = (g * 2 halves), block 256 = 32 cols x 8 segs.
//   new[0] = pa*push + po*S[1] + no*S[0]
//   new[i] = pa*S[i-1] + po*S[i+1] + no*S[i]   (S[128]=0)
// ---------------------------------------------------------------------------
__device__ __forceinline__ float4 f4mix(float pa, const float4 x,
                                        float po, const float4 y,
                                        float pn, const float4 z) {
    float4 r;
    r.x = fmaf(pa, x.x, fmaf(po, y.x, pn * z.x));
    r.y = fmaf(pa, x.y, fmaf(po, y.y, pn * z.y));
    r.z = fmaf(pa, x.z, fmaf(po, y.z, pn * z.z));
    r.w = fmaf(pa, x.w, fmaf(po, y.w, pn * z.w));
    return r;
}

__global__ void __launch_bounds__(256)
stack_kernel(const float* __restrict__ stacks,
             const float* __restrict__ push,
             const float* __restrict__ probs,
             float* __restrict__ out) {
    const int g    = blockIdx.x >> 1;
    const int half = blockIdx.x & 1;
    const int seg  = threadIdx.x >> 5;
    const int col  = threadIdx.x & 31;
    const int rb   = half * 64 + seg * 8;     // 0..120 step 8

    const int b  = g >> 2;
    const int ns = g & 3;
    const float pa = __ldg(&probs[b * 12 + ns * 3 + 0]);
    const float po = __ldg(&probs[b * 12 + ns * 3 + 1]);
    const float no = __ldg(&probs[b * 12 + ns * 3 + 2]);

    const float4* S = (const float4*)stacks + (size_t)g * (SS_ * 32) + col;
    float4*       O = (float4*)out          + (size_t)g * (SS_ * 32) + col;
    const float4  pu = ((const float4*)push)[g * 32 + col];

    float4 v[10];
    v[0] = (rb == 0) ? pu : S[(rb - 1) * 32];
    #pragma unroll
    for (int j = 1; j <= 8; ++j) v[j] = S[(rb + j - 1) * 32];
    v[9] = (rb == 120) ? make_float4(0.f, 0.f, 0.f, 0.f) : S[(rb + 8) * 32];

    #pragma unroll
    for (int i = 0; i < 8; ++i)
        O[(rb + i) * 32] = f4mix(pa, v[i], po, v[i + 2], no, v[i + 1]);
}

// ---------------------------------------------------------------------------
// Launch
// ---------------------------------------------------------------------------
extern "C" void kernel_launch(void* const* d_in, const int* in_sizes, int n_in,
                              void* d_out, int out_size) {
    const float* inputs  = (const float*)d_in[0];
    const float* stacks  = (const float*)d_in[1];
    const float* core    = (const float*)d_in[2];
    const float* W_ih    = (const float*)d_in[3];
    const float* b_ih    = (const float*)d_in[4];
    const float* W_hh    = (const float*)d_in[5];
    const float* b_hh    = (const float*)d_in[6];
    const float* W_push  = (const float*)d_in[7];
    const float* b_push  = (const float*)d_in[8];
    const float* W_act   = (const float*)d_in[9];
    const float* b_act   = (const float*)d_in[10];

    float* out = (float*)d_out;
    float* h_out      = out;               // (B, H)
    float* stacks_out = out + BB * HH;     // (B, NS, SS, CS)

    float *pPh, *pPpa, *ppush, *plog, *pprob;
    cudaGetSymbolAddress((void**)&pPh,   g_Ph);
    cudaGetSymbolAddress((void**)&pPpa,  g_Ppa);
    cudaGetSymbolAddress((void**)&ppush, g_push);
    cudaGetSymbolAddress((void**)&plog,  g_logits);
    cudaGetSymbolAddress((void**)&pprob, g_probs);

    // 1) gemm-h partials:  grid (8,8,4) = 256 CTAs
    gemm_split<0><<<dim3(HH / 64, BB / 64, KSPL), 128>>>(
        nullptr, inputs, stacks, core, W_ih, W_hh, nullptr, nullptr, pPh);

    // 2) h = tanh(sum + biases)
    epi_h<<<BB * HH / 4 / 256, 256>>>(pPh, b_ih, b_hh, h_out);

    // 3) gemm-pa partials: grid (9,8,4) = 288 CTAs
    gemm_split<1><<<dim3(NPA / 64, BB / 64, KSPL), 128>>>(
        h_out, nullptr, nullptr, nullptr, nullptr, nullptr, W_push, W_act, pPpa);

    // 4) push + logits
    epi_pa<<<BB * NPA / 4 / 256, 256>>>(pPpa, b_push, b_act, ppush, plog);

    // 5) softmax probs (once)
    probs_kernel<<<2, 256>>>(plog, pprob);

    // 6) stack shift update
    stack_kernel<<<BB * NS_ * 2, 256>>>(stacks, ppush, pprob, stacks_out);
}